// round 16
// baseline (speedup 1.0000x reference)
#include <cuda_runtime.h>
#include <math.h>

#define N_LEVELS      16
#define HASHMAP_SIZE  (1u << 19)
#define HASH_MASK     (HASHMAP_SIZE - 1u)
#define P2            2654435761u
#define P3            805459861u

struct ResTable {
    int res[N_LEVELS];
};

// 8 lanes per point (one corner each), 4 points per warp.  R14 load pattern.
// Levels processed in pairs (2m, 2m+1); the xor-4 butterfly stage becomes an
// exchange (low lanes keep level 2m, high lanes keep 2m+1), halving SHFL
// count per level while keeping the identical summation tree.
__global__ void __launch_bounds__(256)
hashenc_kernel(const float* __restrict__ pos,
               const float* __restrict__ emb,
               float* __restrict__ out,
               ResTable rt,
               int n_points)
{
    const int tid  = blockIdx.x * blockDim.x + threadIdx.x;
    const int lane = threadIdx.x & 31;
    const int c    = lane & 7;          // corner id: (i<<2)|(j<<1)|k
    const int sub  = lane >> 3;         // point slot within warp (0..3)
    const int p    = (tid >> 5) * 4 + sub;

    const bool valid = (p < n_points);
    const int  pp    = valid ? p : 0;

    const unsigned bi = (c >> 2) & 1;
    const unsigned bj = (c >> 1) & 1;
    const unsigned bk =  c       & 1;

    // weight via FMA: a = s*w + o  (s=+1,o=0 if corner bit set; s=-1,o=1 else)
    const float sxw = bi ? 1.f : -1.f, oxw = bi ? 0.f : 1.f;
    const float syw = bj ? 1.f : -1.f, oyw = bj ? 0.f : 1.f;
    const float szw = bk ? 1.f : -1.f, ozw = bk ? 0.f : 1.f;

    const float px = pos[pp * 3 + 0];
    const float py = pos[pp * 3 + 1];
    const float pz = pos[pp * 3 + 2];

    const bool hi4 = (c & 4) != 0;

    // lane keeps 2 levels: slot0 = pair (c&3), slot1 = pair (c&3)+4
    float2 accA = make_float2(0.f, 0.f);
    float2 accB = make_float2(0.f, 0.f);

#pragma unroll
    for (int m = 0; m < 8; ++m) {
        float xv[2], yv[2];   // weighted corner feats for levels 2m, 2m+1

#pragma unroll
        for (int h = 0; h < 2; ++h) {
            const int l = 2 * m + h;
            const int   res  = rt.res[l];
            const float fres = (float)res;

            const float sx = px * fres, sy = py * fres, sz = pz * fres;
            const float fx = floorf(sx), fy = floorf(sy), fz = floorf(sz);
            const float wx = sx - fx,   wy = sy - fy,   wz = sz - fz;

            const unsigned ux = (unsigned)(int)fx + bi;
            const unsigned uy = (unsigned)(int)fy + bj;
            const unsigned uz = (unsigned)(int)fz + bk;

            const unsigned r1 = (unsigned)(res + 1);
            const bool dense =
                ((long long)r1 * (long long)r1 * (long long)r1) <= (long long)HASHMAP_SIZE;

            unsigned idx;
            if (dense) {
                idx = ux * (r1 * r1) + uy * r1 + uz;
            } else {
                idx = (ux ^ (uy * P2) ^ (uz * P3)) & HASH_MASK;
            }

            const float2* __restrict__ table =
                reinterpret_cast<const float2*>(emb) + (size_t)l * HASHMAP_SIZE;

            float2 f;
            if (l <= 1) f = __ldg(&table[idx]);    // L1-resident coarse tables
            else        f = __ldcg(&table[idx]);   // L2 only

            const float ax = fmaf(sxw, wx, oxw);
            const float ay = fmaf(syw, wy, oyw);
            const float az = fmaf(szw, wz, ozw);
            const float w  = ax * ay * az;

            xv[h] = f.x * w;
            yv[h] = f.y * w;
        }

        // stage xor4 as exchange: low lanes keep level 2m, high keep 2m+1.
        // pairing (c, c^4) identical to the plain butterfly -> same sum tree.
        float X = (hi4 ? xv[1] : xv[0])
                + __shfl_xor_sync(0xffffffffu, hi4 ? xv[0] : xv[1], 4);
        float Y = (hi4 ? yv[1] : yv[0])
                + __shfl_xor_sync(0xffffffffu, hi4 ? yv[0] : yv[1], 4);

        // stages xor2, xor1: full butterflies within each 4-lane half
        X += __shfl_xor_sync(0xffffffffu, X, 2);
        Y += __shfl_xor_sync(0xffffffffu, Y, 2);
        X += __shfl_xor_sync(0xffffffffu, X, 1);
        Y += __shfl_xor_sync(0xffffffffu, Y, 1);

        // lane holds complete sum of its level (2m low / 2m+1 high).
        // keeper: lane with (c&3) == (m&3); slot = m>>2
        if ((m & 3) == (c & 3)) {
            if (m < 4) accA = make_float2(X, Y);
            else       accB = make_float2(X, Y);
        }
    }

    if (valid) {
        // lane c<4 holds levels {2c, 2c+8}; lane c>=4 (q=c-4) holds {2q+1, 2q+9}
        float* __restrict__ ob = out + (size_t)p * 32;
        const int q   = c & 3;
        const int off = 4 * q + (hi4 ? 2 : 0);
        *reinterpret_cast<float2*>(ob + off)      = accA;
        *reinterpret_cast<float2*>(ob + off + 16) = accB;
    }
}

extern "C" void kernel_launch(void* const* d_in, const int* in_sizes, int n_in,
                              void* d_out, int out_size)
{
    const float* positions  = (const float*)d_in[0];   // [N_POINTS, 3] f32
    const float* embeddings = (const float*)d_in[1];   // [16, 2^19, 2] f32
    float*       out        = (float*)d_out;           // [N_POINTS, 32] f32

    const int n_points = in_sizes[0] / 3;

    // Mirror numpy exactly in double precision (libm exp/log/pow)
    ResTable rt;
    const double scale = exp((log(2048.0) - log(16.0)) / 15.0);
    for (int l = 0; l < N_LEVELS; ++l) {
        rt.res[l] = (int)floor(16.0 * pow(scale, (double)l));
    }

    const long long total_threads = (long long)n_points * 8;
    const int threads = 256;
    const int blocks  = (int)((total_threads + threads - 1) / threads);
    hashenc_kernel<<<blocks, threads>>>(positions, embeddings, out, rt, n_points);
}